// round 9
// baseline (speedup 1.0000x reference)
#include <cuda_runtime.h>
#include <cuda_bf16.h>

// MedSegNetV2: 3x3 texture features + martingale.
// Plane-pipelined (double-buffered RAW-ONLY smem, register prefetch).
// plogp recomputed at consume time via MUFU (sl smem array deleted);
// raw 3x6 window register-resident (single smem pass: 3 LDS.128 / 4 px).
// x: [8,64,224,224] f32 -> out: [8,256,224,224] f32, channel = c*4 + feature.

#define IMG_H 224
#define IMG_W 224
#define PLANE (IMG_H * IMG_W)
#define BX 56
#define BY 8
#define NTHR (BX * BY)
#define SROWS (BY + 2)
#define SW 232                    // padded row stride; data at [4..231]
#define PPB 8                     // planes per block

__global__ void __launch_bounds__(NTHR, 3)
medseg7_kernel(const float* __restrict__ x, float* __restrict__ out) {
    __shared__ float sp[2][SROWS][SW];   // raw values only (double buffered)

    const int tx = threadIdx.x, ty = threadIdx.y;
    const int tid = ty * BX + tx;
    const int lane = tid & 31;
    const int y0 = blockIdx.y * BY;
    const int p0 = blockIdx.z * PPB;

    // Zero pad columns (col -1 -> idx 3, col 224 -> idx 228), both buffers.
    // plogp(0) emerges naturally at consume time: 1e-6*log(1e-6).
    if (tid < 2 * SROWS) {
        const int r = tid >> 1;
        const int col = (tid & 1) ? 228 : 3;
        sp[0][r][col] = 0.0f;
        sp[1][r][col] = 0.0f;
    }

    // ---- Plane-invariant load geometry: 560 float4 slots over 448 threads ----
    const int i1 = tid + NTHR;
    const int r0 = tid / 56, c0 = tid - r0 * 56;
    const int r1 = i1 / 56,  c1 = i1 - r1 * 56;
    const int gr0 = y0 + r0 - 1, gr1 = y0 + r1 - 1;
    const bool ok0 = (gr0 >= 0) && (gr0 < IMG_H);
    const bool ok1 = (tid < 112) && (gr1 >= 0) && (gr1 < IMG_H);
    const float* g0 = x + (size_t)p0 * PLANE + (size_t)(ok0 ? gr0 : 0) * IMG_W + c0 * 4;
    const float* g1 = x + (size_t)p0 * PLANE + (size_t)(ok1 ? gr1 : 0) * IMG_W + c1 * 4;

    const bool pL = (lane == 0) || (tx == 0);
    const bool pR = (lane == 31) || (tx == BX - 1);
    const unsigned FULL = 0xFFFFFFFFu;
    const int cb = 4 * tx;

    float* optr = out + (size_t)p0 * 4 * PLANE + (size_t)(y0 + ty) * IMG_W + cb;

    // ---- Prolog: stage plane 0 into buffer 0 ----
    {
        const float4 Z = make_float4(0.f, 0.f, 0.f, 0.f);
        float4 va = ok0 ? *(const float4*)g0 : Z;
        float4 vb = ok1 ? *(const float4*)g1 : Z;
        ((float4*)&sp[0][r0][4])[c0] = va;
        if (tid < 112) ((float4*)&sp[0][r1][4])[c1] = vb;
    }
    __syncthreads();

    int cur = 0;
    #pragma unroll 1
    for (int i = 0; i < PPB; i++) {
        // ---- Prefetch next plane into registers ----
        float4 va, vb;
        const bool more = (i + 1 < PPB);
        if (more) {
            const float4 Z = make_float4(0.f, 0.f, 0.f, 0.f);
            va = ok0 ? *(const float4*)(g0 + (size_t)(i + 1) * PLANE) : Z;
            vb = ok1 ? *(const float4*)(g1 + (size_t)(i + 1) * PLANE) : Z;
        }

        const float (*spc)[SW] = sp[cur];

        // ---- Single smem pass: window -> regs; S1 cols; SL via MUFU ----
        float pr[3][6];
        float cS1[6], SL[4];
        #pragma unroll
        for (int j = 0; j < 6; j++) cS1[j] = 0.f;
        #pragma unroll
        for (int j = 0; j < 4; j++) SL[j] = 0.f;

        #pragma unroll
        for (int r = 0; r < 3; r++) {
            const float* rowp = &spc[ty + r][cb];
            const float4 cp = *(const float4*)(rowp + 4);
            float lp = __shfl_up_sync(FULL, cp.w, 1);   if (pL) lp = rowp[3];
            float rv = __shfl_down_sync(FULL, cp.x, 1); if (pR) rv = rowp[8];

            pr[r][0] = lp;   pr[r][1] = cp.x; pr[r][2] = cp.y;
            pr[r][3] = cp.z; pr[r][4] = cp.w; pr[r][5] = rv;

            float lv[6];
            #pragma unroll
            for (int j = 0; j < 6; j++) {
                cS1[j] += pr[r][j];
                const float c = fmaxf(pr[r][j], 1e-6f);
                lv[j] = c * __logf(c);
            }
            // fold horizontal tri-sum of plogp immediately (keeps live set small)
            const float e1 = lv[1] + lv[2], e2 = lv[2] + lv[3], e3 = lv[3] + lv[4];
            SL[0] += lv[0] + e1;
            SL[1] += e1 + lv[3];
            SL[2] += e2 + lv[4];
            SL[3] += e3 + lv[5];
        }

        // Horizontal tri-sums of S1.
        float S1[4], m[4];
        {
            const float e1 = cS1[1]+cS1[2], e2 = cS1[2]+cS1[3], e3 = cS1[3]+cS1[4];
            S1[0] = cS1[0]+e1; S1[1] = e1+cS1[3]; S1[2] = e2+cS1[4]; S1[3] = e3+cS1[5];
            #pragma unroll
            for (int j = 0; j < 4; j++) m[j] = S1[j] * (1.0f / 9.0f);
        }

        // ---- Register-only pass: column squares + SAD ----
        float cS2[6];
        #pragma unroll
        for (int j = 0; j < 6; j++)
            cS2[j] = fmaf(pr[0][j], pr[0][j],
                     fmaf(pr[1][j], pr[1][j], pr[2][j] * pr[2][j]));

        float S2[4], M2[4];
        {
            const float e1 = cS2[1]+cS2[2], e2 = cS2[2]+cS2[3], e3 = cS2[3]+cS2[4];
            S2[0] = cS2[0]+e1; S2[1] = e1+cS2[3]; S2[2] = e2+cS2[4]; S2[3] = e3+cS2[5];
            #pragma unroll
            for (int j = 0; j < 4; j++) M2[j] = fmaf(-S1[j], m[j], S2[j]);
        }

        float sad[4] = {0.f, 0.f, 0.f, 0.f};
        #pragma unroll
        for (int r = 0; r < 3; r++) {
            #pragma unroll
            for (int j = 0; j < 4; j++) {
                sad[j] += fabsf(pr[r][j]     - m[j]);
                sad[j] += fabsf(pr[r][j + 1] - m[j]);
                sad[j] += fabsf(pr[r][j + 2] - m[j]);
            }
        }

        // ---- Features + martingale ----
        const float C   = 0.6065306597126334f;   // exp(-0.5)
        const float K1  = (8.0f / 9.0f) * C;
        const float KC0 = C / 9e-6f;
        const float KE  = C / 9.0f;
        const float KH  = 9.0f * C;

        float g0f[4], g1f[4], g2f[4], g3f[4];
        #pragma unroll
        for (int j = 0; j < 4; j++) {
            g0f[j] = (M2[j] >= 8e-6f) ? K1 : fmaxf(M2[j] * KC0, 1e-4f);
            g1f[j] = fmaxf(S2[j] * KE, 1e-4f);
            g2f[j] = fmaxf(SL[j] * (-KE), 1e-4f);
            g3f[j] = fmaxf(KH * __frcp_rn(9.0f + sad[j] + 9e-6f), 1e-4f);
        }

        *(float4*)(optr + 0 * PLANE) = make_float4(g0f[0], g0f[1], g0f[2], g0f[3]);
        *(float4*)(optr + 1 * PLANE) = make_float4(g1f[0], g1f[1], g1f[2], g1f[3]);
        *(float4*)(optr + 2 * PLANE) = make_float4(g2f[0], g2f[1], g2f[2], g2f[3]);
        *(float4*)(optr + 3 * PLANE) = make_float4(g3f[0], g3f[1], g3f[2], g3f[3]);
        optr += 4 * PLANE;

        // ---- Stage prefetched plane into the other buffer ----
        if (more) {
            const int nxt = cur ^ 1;
            ((float4*)&sp[nxt][r0][4])[c0] = va;
            if (tid < 112) ((float4*)&sp[nxt][r1][4])[c1] = vb;
            __syncthreads();
        }
        cur ^= 1;
    }
}

extern "C" void kernel_launch(void* const* d_in, const int* in_sizes, int n_in,
                              void* d_out, int out_size) {
    const float* x = (const float*)d_in[0];
    float* out = (float*)d_out;
    dim3 block(BX, BY);                       // 448 threads
    dim3 grid(1, IMG_H / BY, 512 / PPB);      // 28 strips x 64 plane-groups
    medseg7_kernel<<<grid, block>>>(x, out);
}

// round 11
// speedup vs baseline: 1.0970x; 1.0970x over previous
#include <cuda_runtime.h>
#include <cuda_bf16.h>

// MedSegNetV2: 3x3 texture features + martingale.
// R7 pipeline (double-buffered sp+sl smem, register prefetch) widened to
// 8 px/thread: per-thread fixed costs (shfl, seams, pointers) amortized 2x,
// LDS traffic per pixel nearly halved.
// x: [8,64,224,224] f32 -> out: [8,256,224,224] f32, channel = c*4 + feature.

#define IMG_H 224
#define IMG_W 224
#define PLANE (IMG_H * IMG_W)
#define BX 28                     // threads in x, 8 px each -> full 224-wide row
#define BY 8
#define NTHR (BX * BY)            // 224
#define SROWS (BY + 2)
#define SW 232                    // padded row stride; data at [4..227], pads 3/228
#define PPB 8                     // planes per block
#define PL0 (-1.3815511e-5f)      // 1e-6 * ln(1e-6)

__device__ __forceinline__ float4 plogp4(float4 v) {
    float4 l; float c;
    c = fmaxf(v.x, 1e-6f); l.x = c * __logf(c);
    c = fmaxf(v.y, 1e-6f); l.y = c * __logf(c);
    c = fmaxf(v.z, 1e-6f); l.z = c * __logf(c);
    c = fmaxf(v.w, 1e-6f); l.w = c * __logf(c);
    return l;
}

__global__ void __launch_bounds__(NTHR, 5)
medseg8_kernel(const float* __restrict__ x, float* __restrict__ out) {
    __shared__ float sp[2][SROWS][SW];   // raw values (double buffered)
    __shared__ float sl[2][SROWS][SW];   // c*log(c)

    const int tx = threadIdx.x, ty = threadIdx.y;
    const int tid = ty * BX + tx;
    const int lane = tid & 31;
    const int y0 = blockIdx.y * BY;
    const int p0 = blockIdx.z * PPB;

    // Constant pad columns, both buffers.
    if (tid < 2 * SROWS) {
        const int r = tid >> 1;
        const int col = (tid & 1) ? 228 : 3;
        sp[0][r][col] = 0.0f;  sp[1][r][col] = 0.0f;
        sl[0][r][col] = PL0;   sl[1][r][col] = PL0;
    }

    // ---- Plane-invariant load geometry: 560 float4 slots over 224 threads ----
    const int iA = tid, iB = tid + NTHR, iC = tid + 2 * NTHR;
    const int rA = iA / 56, cA = iA - rA * 56;
    const int rB = iB / 56, cB = iB - rB * 56;
    const int rC = iC / 56, cC = iC - rC * 56;
    const int gA = y0 + rA - 1, gB = y0 + rB - 1, gC = y0 + rC - 1;
    const bool okA = (gA >= 0) && (gA < IMG_H);
    const bool okB = (gB >= 0) && (gB < IMG_H);
    const bool okC = (tid < 112) && (gC >= 0) && (gC < IMG_H);
    const float* pA = x + (size_t)p0 * PLANE + (size_t)(okA ? gA : 0) * IMG_W + cA * 4;
    const float* pB = x + (size_t)p0 * PLANE + (size_t)(okB ? gB : 0) * IMG_W + cB * 4;
    const float* pC = x + (size_t)p0 * PLANE + (size_t)(okC ? gC : 0) * IMG_W + cC * 4;

    const bool prL = (lane == 0) || (tx == 0);
    const bool prR = (lane == 31) || (tx == BX - 1);
    const unsigned FULL = 0xFFFFFFFFu;
    const int cbase = 8 * tx;

    float* optr = out + (size_t)p0 * 4 * PLANE + (size_t)(y0 + ty) * IMG_W + cbase;

    // ---- Prolog: stage plane 0 ----
    {
        const float4 Z = make_float4(0.f, 0.f, 0.f, 0.f);
        const float4 a = okA ? *(const float4*)pA : Z;
        const float4 b = okB ? *(const float4*)pB : Z;
        const float4 c = okC ? *(const float4*)pC : Z;
        ((float4*)&sp[0][rA][4])[cA] = a; ((float4*)&sl[0][rA][4])[cA] = plogp4(a);
        ((float4*)&sp[0][rB][4])[cB] = b; ((float4*)&sl[0][rB][4])[cB] = plogp4(b);
        if (tid < 112) {
            ((float4*)&sp[0][rC][4])[cC] = c; ((float4*)&sl[0][rC][4])[cC] = plogp4(c);
        }
    }
    __syncthreads();

    int cur = 0;
    #pragma unroll 1
    for (int i = 0; i < PPB; i++) {
        // ---- Prefetch next plane ----
        float4 va, vb, vc;
        const bool more = (i + 1 < PPB);
        if (more) {
            const float4 Z = make_float4(0.f, 0.f, 0.f, 0.f);
            const size_t off = (size_t)(i + 1) * PLANE;
            va = okA ? *(const float4*)(pA + off) : Z;
            vb = okB ? *(const float4*)(pB + off) : Z;
            vc = okC ? *(const float4*)(pC + off) : Z;
        }

        const float (*spc)[SW] = sp[cur];
        const float (*slc)[SW] = sl[cur];

        // ---- Pass 1: column sums S1, SL over 10 cols x 3 rows ----
        float cS1[10], cSL[10], lpx[3], rvx[3];
        #pragma unroll
        for (int j = 0; j < 10; j++) { cS1[j] = 0.f; cSL[j] = 0.f; }

        #pragma unroll
        for (int r = 0; r < 3; r++) {
            const float* rowp = &spc[ty + r][cbase];
            const float* rowl = &slc[ty + r][cbase];
            const float4 a  = *(const float4*)(rowp + 4);
            const float4 b  = *(const float4*)(rowp + 8);
            const float4 la = *(const float4*)(rowl + 4);
            const float4 lb = *(const float4*)(rowl + 8);
            float lp = __shfl_up_sync(FULL, b.w, 1);    if (prL) lp = rowp[3];
            float ll = __shfl_up_sync(FULL, lb.w, 1);   if (prL) ll = rowl[3];
            float rv = __shfl_down_sync(FULL, a.x, 1);  if (prR) rv = rowp[12];
            float rl = __shfl_down_sync(FULL, la.x, 1); if (prR) rl = rowl[12];
            lpx[r] = lp; rvx[r] = rv;

            const float pv[10] = { lp, a.x, a.y, a.z, a.w, b.x, b.y, b.z, b.w, rv };
            const float lv[10] = { ll, la.x, la.y, la.z, la.w, lb.x, lb.y, lb.z, lb.w, rl };
            #pragma unroll
            for (int j = 0; j < 10; j++) {
                cS1[j] += pv[j];
                cSL[j] += lv[j];
            }
        }

        // m from tri-sums of cS1 (S1 not kept: M2 = S2 - 9*m^2).
        float m[8];
        #pragma unroll
        for (int j = 0; j < 8; j++)
            m[j] = (cS1[j] + cS1[j + 1] + cS1[j + 2]) * (1.0f / 9.0f);

        // Entropy: finalize + store NOW (frees cSL before pass 2).
        const float C   = 0.6065306597126334f;   // exp(-0.5)
        const float KE  = C / 9.0f;
        {
            float g2[8];
            #pragma unroll
            for (int j = 0; j < 8; j++)
                g2[j] = fmaxf((cSL[j] + cSL[j + 1] + cSL[j + 2]) * (-KE), 1e-4f);
            *(float4*)(optr + 2 * PLANE)     = make_float4(g2[0], g2[1], g2[2], g2[3]);
            *(float4*)(optr + 2 * PLANE + 4) = make_float4(g2[4], g2[5], g2[6], g2[7]);
        }

        // ---- Pass 2: re-read central rows; column squares + SAD ----
        float cS2[10], sad[8];
        #pragma unroll
        for (int j = 0; j < 10; j++) cS2[j] = 0.f;
        #pragma unroll
        for (int j = 0; j < 8; j++) sad[j] = 0.f;

        #pragma unroll
        for (int r = 0; r < 3; r++) {
            const float* rowp = &spc[ty + r][cbase];
            const float4 a = *(const float4*)(rowp + 4);
            const float4 b = *(const float4*)(rowp + 8);
            const float pv[10] = { lpx[r], a.x, a.y, a.z, a.w,
                                   b.x, b.y, b.z, b.w, rvx[r] };
            #pragma unroll
            for (int j = 0; j < 10; j++) cS2[j] = fmaf(pv[j], pv[j], cS2[j]);
            #pragma unroll
            for (int j = 0; j < 8; j++) {
                sad[j] += fabsf(pv[j]     - m[j]);
                sad[j] += fabsf(pv[j + 1] - m[j]);
                sad[j] += fabsf(pv[j + 2] - m[j]);
            }
        }

        // ---- Contrast / energy / homogeneity ----
        const float K1  = (8.0f / 9.0f) * C;
        const float KC0 = C / 9e-6f;
        const float KH  = 9.0f * C;

        float g0[8], g1[8], g3[8];
        #pragma unroll
        for (int j = 0; j < 8; j++) {
            const float S2 = cS2[j] + cS2[j + 1] + cS2[j + 2];
            const float M2 = fmaf(-9.0f * m[j], m[j], S2);
            g0[j] = (M2 >= 8e-6f) ? K1 : fmaxf(M2 * KC0, 1e-4f);
            g1[j] = fmaxf(S2 * KE, 1e-4f);
            g3[j] = fmaxf(KH * __frcp_rn(9.0f + sad[j] + 9e-6f), 1e-4f);
        }

        *(float4*)(optr + 0 * PLANE)     = make_float4(g0[0], g0[1], g0[2], g0[3]);
        *(float4*)(optr + 0 * PLANE + 4) = make_float4(g0[4], g0[5], g0[6], g0[7]);
        *(float4*)(optr + 1 * PLANE)     = make_float4(g1[0], g1[1], g1[2], g1[3]);
        *(float4*)(optr + 1 * PLANE + 4) = make_float4(g1[4], g1[5], g1[6], g1[7]);
        *(float4*)(optr + 3 * PLANE)     = make_float4(g3[0], g3[1], g3[2], g3[3]);
        *(float4*)(optr + 3 * PLANE + 4) = make_float4(g3[4], g3[5], g3[6], g3[7]);
        optr += 4 * PLANE;

        // ---- Stage prefetched plane into the other buffer ----
        if (more) {
            const int nxt = cur ^ 1;
            ((float4*)&sp[nxt][rA][4])[cA] = va; ((float4*)&sl[nxt][rA][4])[cA] = plogp4(va);
            ((float4*)&sp[nxt][rB][4])[cB] = vb; ((float4*)&sl[nxt][rB][4])[cB] = plogp4(vb);
            if (tid < 112) {
                ((float4*)&sp[nxt][rC][4])[cC] = vc; ((float4*)&sl[nxt][rC][4])[cC] = plogp4(vc);
            }
            __syncthreads();
        }
        cur ^= 1;
    }
}

extern "C" void kernel_launch(void* const* d_in, const int* in_sizes, int n_in,
                              void* d_out, int out_size) {
    const float* x = (const float*)d_in[0];
    float* out = (float*)d_out;
    dim3 block(BX, BY);                       // 224 threads
    dim3 grid(1, IMG_H / BY, 512 / PPB);      // 28 strips x 64 plane-groups
    medseg8_kernel<<<grid, block>>>(x, out);
}

// round 12
// speedup vs baseline: 1.3874x; 1.2647x over previous
#include <cuda_runtime.h>
#include <cuda_bf16.h>

// MedSegNetV2: 3x3 texture features + martingale — register-rolling march.
// One warp = one full 224-wide row (28 lanes x 8 px), marching down a 16-row
// chunk of one plane. 3-row window lives in a register ring; NO shared memory,
// NO barriers. Each input row: one LDG.128x2, reused for 3 output rows.
// x: [8,64,224,224] f32 -> out: [8,256,224,224] f32, channel = c*4 + feature.

#define IMG_H 224
#define IMG_W 224
#define PLANE (IMG_H * IMG_W)
#define CH 16
#define CHUNKS (IMG_H / CH)       // 14
#define PL0 (-1.3815511e-5f)      // 1e-6 * ln(1e-6)

// martingale constants (validated rel_err ~1e-7 since R2)
#define MC   0.6065306597126334f          // exp(-0.5)
#define K1   ((8.0f / 9.0f) * MC)         // contrast, normal branch
#define KC0  (MC / 9e-6f)                 // contrast, tiny-variance branch
#define KE   (MC / 9.0f)                  // energy / entropy scale
#define KH   (9.0f * MC)                  // homogeneity scale

#define FETCH(y) do {                                                         \
    if ((unsigned)(y) < IMG_H) {                                              \
        fa = *(const float4*)(base + (size_t)(y) * IMG_W);                    \
        fb = *(const float4*)(base + (size_t)(y) * IMG_W + 4);                \
    } else {                                                                  \
        fa = make_float4(0.f, 0.f, 0.f, 0.f);                                 \
        fb = make_float4(0.f, 0.f, 0.f, 0.f);                                 \
    }                                                                         \
} while (0)

// Consume fa/fb (one image row) into ring slot s: raw values + plogp tri-sums.
#define ROWPROC(s) do {                                                       \
    float nl = __shfl_up_sync(FULL, fb.w, 1);   if (L0)  nl = 0.f;            \
    float nr = __shfl_down_sync(FULL, fa.x, 1); if (R27) nr = 0.f;            \
    pr[s][0] = nl;   pr[s][1] = fa.x; pr[s][2] = fa.y; pr[s][3] = fa.z;       \
    pr[s][4] = fa.w; pr[s][5] = fb.x; pr[s][6] = fb.y; pr[s][7] = fb.z;       \
    pr[s][8] = fb.w; pr[s][9] = nr;                                           \
    float lo[10];                                                             \
    _Pragma("unroll")                                                         \
    for (int j = 1; j <= 8; j++) {                                            \
        const float c = fmaxf(pr[s][j], 1e-6f);                               \
        lo[j] = c * __logf(c);                                                \
    }                                                                         \
    lo[0] = __shfl_up_sync(FULL, lo[8], 1);   if (L0)  lo[0] = PL0;           \
    lo[9] = __shfl_down_sync(FULL, lo[1], 1); if (R27) lo[9] = PL0;           \
    _Pragma("unroll")                                                         \
    for (int j = 0; j < 8; j++) hl[s][j] = lo[j] + lo[j + 1] + lo[j + 2];     \
} while (0)

// Emit output row y from ring slots s0 (y-1), s1 (y), s2 (y+1).
#define OUTPUT(s0, s1, s2, y) do {                                            \
    float cS1[10], cS2[10];                                                   \
    _Pragma("unroll")                                                         \
    for (int j = 0; j < 10; j++) {                                            \
        cS1[j] = pr[s0][j] + pr[s1][j] + pr[s2][j];                           \
        cS2[j] = fmaf(pr[s0][j], pr[s0][j],                                   \
                 fmaf(pr[s1][j], pr[s1][j], pr[s2][j] * pr[s2][j]));          \
    }                                                                         \
    float m[8], M2s[8], g[8];                                                 \
    _Pragma("unroll")                                                         \
    for (int j = 0; j < 8; j++)                                               \
        m[j] = (cS1[j] + cS1[j + 1] + cS1[j + 2]) * (1.0f / 9.0f);            \
    float* o = obase + (size_t)(y) * IMG_W;                                   \
    _Pragma("unroll")                                                         \
    for (int j = 0; j < 8; j++) {                                             \
        const float S2 = cS2[j] + cS2[j + 1] + cS2[j + 2];                    \
        M2s[j] = fmaf(-9.0f * m[j], m[j], S2);                                \
        g[j] = fmaxf(S2 * KE, 1e-4f);                                         \
    }                                                                         \
    if (act) {                                                                \
        *(float4*)(o + PLANE)     = make_float4(g[0], g[1], g[2], g[3]);      \
        *(float4*)(o + PLANE + 4) = make_float4(g[4], g[5], g[6], g[7]);      \
    }                                                                         \
    _Pragma("unroll")                                                         \
    for (int j = 0; j < 8; j++)                                               \
        g[j] = (M2s[j] >= 8e-6f) ? K1 : fmaxf(M2s[j] * KC0, 1e-4f);           \
    if (act) {                                                                \
        *(float4*)(o)     = make_float4(g[0], g[1], g[2], g[3]);              \
        *(float4*)(o + 4) = make_float4(g[4], g[5], g[6], g[7]);              \
    }                                                                         \
    _Pragma("unroll")                                                         \
    for (int j = 0; j < 8; j++)                                               \
        g[j] = fmaxf((hl[s0][j] + hl[s1][j] + hl[s2][j]) * (-KE), 1e-4f);     \
    if (act) {                                                                \
        *(float4*)(o + 2 * PLANE)     = make_float4(g[0], g[1], g[2], g[3]);  \
        *(float4*)(o + 2 * PLANE + 4) = make_float4(g[4], g[5], g[6], g[7]);  \
    }                                                                         \
    _Pragma("unroll")                                                         \
    for (int j = 0; j < 8; j++) {                                             \
        float sad = 0.f;                                                      \
        _Pragma("unroll")                                                     \
        for (int k = 0; k < 3; k++) {                                         \
            sad += fabsf(pr[s0][j + k] - m[j]);                               \
            sad += fabsf(pr[s1][j + k] - m[j]);                               \
            sad += fabsf(pr[s2][j + k] - m[j]);                               \
        }                                                                     \
        g[j] = fmaxf(KH * __frcp_rn(9.0f + sad + 9e-6f), 1e-4f);              \
    }                                                                         \
    if (act) {                                                                \
        *(float4*)(o + 3 * PLANE)     = make_float4(g[0], g[1], g[2], g[3]);  \
        *(float4*)(o + 3 * PLANE + 4) = make_float4(g[4], g[5], g[6], g[7]);  \
    }                                                                         \
} while (0)

__global__ void __launch_bounds__(128, 5)
medseg9_kernel(const float* __restrict__ x, float* __restrict__ out) {
    const int lane = threadIdx.x & 31;
    const int task = blockIdx.x * 4 + (threadIdx.x >> 5);  // 7168 warp-tasks
    const int plane = task / CHUNKS;
    const int chunk = task - plane * CHUNKS;
    const int ys = chunk * CH;
    const int col = 8 * (lane < 28 ? lane : 27);  // lanes 28-31: duplicate, unused
    const bool act = (lane < 28);
    const bool L0  = (lane == 0);
    const bool R27 = (lane >= 27);
    const unsigned FULL = 0xFFFFFFFFu;

    const float* __restrict__ base = x + (size_t)plane * PLANE + col;
    float* __restrict__ obase = out + (size_t)plane * 4 * PLANE + col;

    float pr[3][10];   // raw 3-row window ring (cols -1..8 relative to own 8)
    float hl[3][8];    // plogp horizontal tri-sums ring
    float4 fa, fb;     // in-flight row

    // Prolog: rows ys-1, ys into slots 0,1; prefetch row ys+1.
    FETCH(ys - 1); ROWPROC(0);
    FETCH(ys);     ROWPROC(1);
    FETCH(ys + 1);

    // Main march: row ys+k lands in slot (k+1)%3. 15 rows in 5 triple-steps,
    // each step: consume in-flight row, fire next LDG, emit one output row.
    #pragma unroll 1
    for (int r = 0; r < 15; r += 3) {
        ROWPROC(2); FETCH(ys + r + 2); OUTPUT(0, 1, 2, ys + r);
        ROWPROC(0); FETCH(ys + r + 3); OUTPUT(1, 2, 0, ys + r + 1);
        ROWPROC(1); FETCH(ys + r + 4); OUTPUT(2, 0, 1, ys + r + 2);
    }
    // Epilog: fa/fb holds row ys+16 -> slot 2; emit row ys+15.
    ROWPROC(2);
    OUTPUT(0, 1, 2, ys + 15);
}

extern "C" void kernel_launch(void* const* d_in, const int* in_sizes, int n_in,
                              void* d_out, int out_size) {
    const float* x = (const float*)d_in[0];
    float* out = (float*)d_out;
    // 512 planes x 14 chunks = 7168 warp-tasks; 4 warps per 128-thread block.
    medseg9_kernel<<<7168 / 4, 128>>>(x, out);
}